// round 7
// baseline (speedup 1.0000x reference)
#include <cuda_runtime.h>
#include <cstdint>

#define NN 100000
#define EE 1600000
#define SLOPE 0.2f

#define SZ1 (256 * 256)
#define SZ2 (256 * 128)
#define SZ3 (128 * 128)

// ---------------- static device scratch (no cudaMalloc allowed) --------------
__device__ float g_z[NN * 256];     // GEMM output / per-layer features z
__device__ float g_x[NN * 256];     // activation buffer between layers
__device__ float g_el[NN * 8];
__device__ float g_er[NN * 8];
__device__ float g_ex[EE * 8];      // per-edge exp(leakyrelu(e)) in CSR order
__device__ int   g_counts[NN];
__device__ int   g_cursor[NN];
__device__ int   g_rowstart[NN + 1];
__device__ int   g_csr[EE];         // src per CSR slot
__device__ int   g_dstslot[EE];     // dst per CSR slot
__device__ float g_btH[SZ1 + SZ2 + SZ3];  // W^T, tf32 hi parts (bit patterns)
__device__ float g_btL[SZ1 + SZ2 + SZ3];  // W^T, tf32 lo parts

// ---------------- tf32 helpers ----------------------------------------------
__device__ __forceinline__ uint32_t f2tf32(float v) {
    uint32_t r;
    asm("cvt.rna.tf32.f32 %0, %1;" : "=r"(r) : "f"(v));
    return r;
}
__device__ __forceinline__ void mma_tf32(float* d,
    uint32_t a0, uint32_t a1, uint32_t a2, uint32_t a3,
    uint32_t b0, uint32_t b1) {
    asm volatile(
        "mma.sync.aligned.m16n8k8.row.col.f32.tf32.tf32.f32 "
        "{%0,%1,%2,%3}, {%4,%5,%6,%7}, {%8,%9}, {%0,%1,%2,%3};"
        : "+f"(d[0]), "+f"(d[1]), "+f"(d[2]), "+f"(d[3])
        : "r"(a0), "r"(a1), "r"(a2), "r"(a3), "r"(b0), "r"(b1));
}

// ---------------- weight transpose + tf32 split ------------------------------
// BtH[n][k], BtL[n][k] = split(B[k][n])
__global__ void k_transpose(const float* __restrict__ B,
                            float* __restrict__ BtH, float* __restrict__ BtL,
                            int K, int Nc) {
    __shared__ float tile[32][33];
    int bx = blockIdx.x * 32, by = blockIdx.y * 32;  // bx: n, by: k
    int x = threadIdx.x, y = threadIdx.y;            // 32 x 8
    for (int i = y; i < 32; i += 8)
        tile[i][x] = B[(size_t)(by + i) * Nc + bx + x];
    __syncthreads();
    for (int i = y; i < 32; i += 8) {
        float v = tile[x][i];
        uint32_t hi = f2tf32(v);
        uint32_t lo = f2tf32(v - __uint_as_float(hi));
        size_t idx = (size_t)(bx + i) * K + by + x;
        BtH[idx] = __uint_as_float(hi);
        BtL[idx] = __uint_as_float(lo);
    }
}

// ---------------- single-block exclusive scan counts -> rowstart -------------
__global__ void k_scanA() {
    __shared__ int wsum[32];
    int t = threadIdx.x;
    int lane = t & 31, w = t >> 5;
    int base = 0;
    const int NCH = (NN + 1023) / 1024;
    for (int c = 0; c < NCH; c++) {
        int i = c * 1024 + t;
        int v = (i < NN) ? g_counts[i] : 0;
        int x = v;
#pragma unroll
        for (int o = 1; o < 32; o <<= 1) {
            int y = __shfl_up_sync(0xffffffffu, x, o);
            if (lane >= o) x += y;
        }
        if (lane == 31) wsum[w] = x;
        __syncthreads();
        if (w == 0) {
            int s = wsum[lane];
#pragma unroll
            for (int o = 1; o < 32; o <<= 1) {
                int y = __shfl_up_sync(0xffffffffu, s, o);
                if (lane >= o) s += y;
            }
            wsum[lane] = s;
        }
        __syncthreads();
        int incl = x + (w > 0 ? wsum[w - 1] : 0);
        if (i < NN) g_rowstart[i] = base + incl - v;  // exclusive
        base += wsum[31];
        __syncthreads();
    }
    if (t == 0) g_rowstart[NN] = EE;
}

// ---------------- scatter + fused layer-1 edge exp (H=8) ---------------------
__global__ void k_scatter_exp(const int* __restrict__ src,
                              const int* __restrict__ dst,
                              const float* __restrict__ el,
                              const float* __restrict__ er) {
    int e = blockIdx.x * blockDim.x + threadIdx.x;
    if (e >= EE) return;
    int s = src[e], d = dst[e];
    int pos = g_rowstart[d] + atomicAdd(&g_cursor[d], 1);
    g_csr[pos] = s;
    g_dstslot[pos] = d;
    float4 el0 = *(const float4*)(el + (size_t)s * 8);
    float4 el1 = *(const float4*)(el + (size_t)s * 8 + 4);
    float4 er0 = *(const float4*)(er + (size_t)d * 8);
    float4 er1 = *(const float4*)(er + (size_t)d * 8 + 4);
    float ev[8] = {el0.x + er0.x, el0.y + er0.y, el0.z + er0.z, el0.w + er0.w,
                   el1.x + er1.x, el1.y + er1.y, el1.z + er1.z, el1.w + er1.w};
    float ox[8];
#pragma unroll
    for (int h = 0; h < 8; h++) {
        float v = ev[h] > 0.f ? ev[h] : SLOPE * ev[h];
        ox[h] = __expf(v);
    }
    *(float4*)(g_ex + (size_t)pos * 8) = make_float4(ox[0], ox[1], ox[2], ox[3]);
    *(float4*)(g_ex + (size_t)pos * 8 + 4) = make_float4(ox[4], ox[5], ox[6], ox[7]);
}

// ---------------- flat per-edge exp for layers 2/3 ---------------------------
template <int H>
__global__ void k_edgeexp(const float* __restrict__ el,
                          const float* __restrict__ er) {
    int p = blockIdx.x * blockDim.x + threadIdx.x;
    if (p >= EE) return;
    int s = g_csr[p], d = g_dstslot[p];
    if (H == 4) {
        float4 a = *(const float4*)(el + (size_t)s * 4);
        float4 b = *(const float4*)(er + (size_t)d * 4);
        float ev[4] = {a.x + b.x, a.y + b.y, a.z + b.z, a.w + b.w};
        float ox[4];
#pragma unroll
        for (int h = 0; h < 4; h++) {
            float v = ev[h] > 0.f ? ev[h] : SLOPE * ev[h];
            ox[h] = __expf(v);
        }
        *(float4*)(g_ex + (size_t)p * 4) = make_float4(ox[0], ox[1], ox[2], ox[3]);
    } else {  // H == 1
        float v = el[s] + er[d];
        v = v > 0.f ? v : SLOPE * v;
        g_ex[p] = __expf(v);
    }
}

// ---------------- tf32x3 tensor-core GEMM + fused score epilogue ------------
// C[M,Nc] = A[M,K] @ B[K,Nc]; BtH/BtL = pre-split B^T ([Nc,K], tf32 bits).
// 256 thr, 8 warps (2m x 4n), block tile 128x128x8, warp tile 64x32.
// mma.m16n8k8 tf32, 3-term (Ah*Bh + Ah*Bl + Al*Bh). A split in registers.
// Static smem: As[2][128][12] | BsH[2][128][12] | BsL[2][128][12] = 36864 B.
template <int H, int D, bool HIST>
__global__ void __launch_bounds__(256, 2) k_mmagemm(
    const float* __restrict__ A, const float* __restrict__ BtH,
    const float* __restrict__ BtL, float* __restrict__ C,
    const float* __restrict__ al, const float* __restrict__ ar,
    float* __restrict__ el, float* __restrict__ er,
    const int* __restrict__ dst, int M, int Nc, int K) {
    __shared__ float AsB[2 * 128 * 12];
    __shared__ float BHB[2 * 128 * 12];
    __shared__ float BLB[2 * 128 * 12];
#define ASM_(b, r, k) AsB[(b) * 1536 + (r) * 12 + (k)]
#define BHM_(b, r, k) BHB[(b) * 1536 + (r) * 12 + (k)]
#define BLM_(b, r, k) BLB[(b) * 1536 + (r) * 12 + (k)]

    int tid = threadIdx.x;
    if (HIST) {
        int nthr = gridDim.x * gridDim.y * 256;
        int id = (blockIdx.y * gridDim.x + blockIdx.x) * 256 + tid;
        for (int e = id; e < EE; e += nthr) atomicAdd(&g_counts[dst[e]], 1);
    }
    int brow = blockIdx.x * 128;
    int bcol = blockIdx.y * 128;
    int warp = tid >> 5, lane = tid & 31;
    int wm = warp >> 2, wn = warp & 3;
    int g = lane >> 2, cq = lane & 3;

    int ldrow = tid >> 1;            // 0..127
    int c0 = (tid & 1) * 4;          // 0 or 4
    bool aval = (brow + ldrow) < M;
    const float* Ap = A + (size_t)(brow + ldrow) * K + c0;
    const float* BHp = BtH + (size_t)(bcol + ldrow) * K + c0;
    const float* BLp = BtL + (size_t)(bcol + ldrow) * K + c0;

    float acc[4][4][4];
#pragma unroll
    for (int i = 0; i < 4; i++)
#pragma unroll
        for (int j = 0; j < 4; j++)
#pragma unroll
            for (int q = 0; q < 4; q++) acc[i][j][q] = 0.f;

    int nt = K >> 3;
    const float4 F4Z = make_float4(0.f, 0.f, 0.f, 0.f);

    {   // tile 0
        *(float4*)&ASM_(0, ldrow, c0) = aval ? *(const float4*)Ap : F4Z;
        *(float4*)&BHM_(0, ldrow, c0) = *(const float4*)BHp;
        *(float4*)&BLM_(0, ldrow, c0) = *(const float4*)BLp;
    }
    __syncthreads();

    int cur = 0;
    for (int kt = 0; kt < nt; kt++) {
        float4 pa, pbh, pbl;
        bool more = (kt + 1) < nt;
        if (more) {
            int ko = (kt + 1) << 3;
            pa = aval ? *(const float4*)(Ap + ko) : F4Z;
            pbh = *(const float4*)(BHp + ko);
            pbl = *(const float4*)(BLp + ko);
        }
        // B fragments straight from pre-split smem
        uint32_t bh[4][2], bl[4][2];
#pragma unroll
        for (int ni = 0; ni < 4; ni++) {
            int rB = wn * 32 + ni * 8 + g;
            bh[ni][0] = __float_as_uint(BHM_(cur, rB, cq));
            bh[ni][1] = __float_as_uint(BHM_(cur, rB, 4 + cq));
            bl[ni][0] = __float_as_uint(BLM_(cur, rB, cq));
            bl[ni][1] = __float_as_uint(BLM_(cur, rB, 4 + cq));
        }
#pragma unroll
        for (int mi = 0; mi < 4; mi++) {
            int rA = wm * 64 + mi * 16 + g;
            float a0 = ASM_(cur, rA, cq);
            float a1 = ASM_(cur, rA + 8, cq);
            float a2 = ASM_(cur, rA, 4 + cq);
            float a3 = ASM_(cur, rA + 8, 4 + cq);
            uint32_t ah0 = f2tf32(a0), ah1 = f2tf32(a1);
            uint32_t ah2 = f2tf32(a2), ah3 = f2tf32(a3);
            uint32_t al0 = f2tf32(a0 - __uint_as_float(ah0));
            uint32_t al1 = f2tf32(a1 - __uint_as_float(ah1));
            uint32_t al2 = f2tf32(a2 - __uint_as_float(ah2));
            uint32_t al3 = f2tf32(a3 - __uint_as_float(ah3));
#pragma unroll
            for (int ni = 0; ni < 4; ni++) {
                mma_tf32(acc[mi][ni], ah0, ah1, ah2, ah3, bh[ni][0], bh[ni][1]);
                mma_tf32(acc[mi][ni], ah0, ah1, ah2, ah3, bl[ni][0], bl[ni][1]);
                mma_tf32(acc[mi][ni], al0, al1, al2, al3, bh[ni][0], bh[ni][1]);
            }
        }
        if (more) {
            int nb = cur ^ 1;
            *(float4*)&ASM_(nb, ldrow, c0) = pa;
            *(float4*)&BHM_(nb, ldrow, c0) = pbh;
            *(float4*)&BLM_(nb, ldrow, c0) = pbl;
            __syncthreads();
            cur = nb;
        }
    }

    // ---- C store ----
#pragma unroll
    for (int mi = 0; mi < 4; mi++) {
        int r0 = brow + wm * 64 + mi * 16 + g;
#pragma unroll
        for (int ni = 0; ni < 4; ni++) {
            int cgl = bcol + wn * 32 + ni * 8 + cq * 2;
            if (r0 < M)
                *(float2*)(C + (size_t)r0 * Nc + cgl) =
                    make_float2(acc[mi][ni][0], acc[mi][ni][1]);
            if (r0 + 8 < M)
                *(float2*)(C + (size_t)(r0 + 8) * Nc + cgl) =
                    make_float2(acc[mi][ni][2], acc[mi][ni][3]);
        }
    }

    // ---- fused attention-score epilogue ----
    // al/ar are flattened [H*D]; global col (bcol+dl) is the (h,d) flat index
    // for D==32 layers; dl for D==128 (bcol==0).
    float alv[8], arv[8];
#pragma unroll
    for (int ni = 0; ni < 4; ni++)
#pragma unroll
        for (int q = 0; q < 2; q++) {
            int dl = wn * 32 + ni * 8 + cq * 2 + q;
            int idx = (D == 32) ? (bcol + dl) : dl;
            alv[ni * 2 + q] = al[idx];
            arv[ni * 2 + q] = ar[idx];
        }

    if (D == 32) {
        int h = (bcol >> 5) + wn;  // global head index
#pragma unroll
        for (int mi = 0; mi < 4; mi++) {
            float pel0 = 0, per0 = 0, pel1 = 0, per1 = 0;
#pragma unroll
            for (int ni = 0; ni < 4; ni++) {
                pel0 += acc[mi][ni][0] * alv[ni * 2] + acc[mi][ni][1] * alv[ni * 2 + 1];
                per0 += acc[mi][ni][0] * arv[ni * 2] + acc[mi][ni][1] * arv[ni * 2 + 1];
                pel1 += acc[mi][ni][2] * alv[ni * 2] + acc[mi][ni][3] * alv[ni * 2 + 1];
                per1 += acc[mi][ni][2] * arv[ni * 2] + acc[mi][ni][3] * arv[ni * 2 + 1];
            }
#pragma unroll
            for (int o = 1; o < 4; o <<= 1) {
                pel0 += __shfl_xor_sync(0xffffffffu, pel0, o);
                per0 += __shfl_xor_sync(0xffffffffu, per0, o);
                pel1 += __shfl_xor_sync(0xffffffffu, pel1, o);
                per1 += __shfl_xor_sync(0xffffffffu, per1, o);
            }
            if (cq == 0) {
                int r0 = brow + wm * 64 + mi * 16 + g;
                if (r0 < M) {
                    el[(size_t)r0 * H + h] = pel0;
                    er[(size_t)r0 * H + h] = per0;
                }
                if (r0 + 8 < M) {
                    el[(size_t)(r0 + 8) * H + h] = pel1;
                    er[(size_t)(r0 + 8) * H + h] = per1;
                }
            }
        }
    } else {  // D == 128, H == 1, bcol == 0, Nc == 128
        __syncthreads();  // done with tile smem; reuse as reduction scratch
        float* sEl = AsB;        // [128][4]
        float* sEr = AsB + 512;
#pragma unroll
        for (int mi = 0; mi < 4; mi++) {
            float pel0 = 0, per0 = 0, pel1 = 0, per1 = 0;
#pragma unroll
            for (int ni = 0; ni < 4; ni++) {
                pel0 += acc[mi][ni][0] * alv[ni * 2] + acc[mi][ni][1] * alv[ni * 2 + 1];
                per0 += acc[mi][ni][0] * arv[ni * 2] + acc[mi][ni][1] * arv[ni * 2 + 1];
                pel1 += acc[mi][ni][2] * alv[ni * 2] + acc[mi][ni][3] * alv[ni * 2 + 1];
                per1 += acc[mi][ni][2] * arv[ni * 2] + acc[mi][ni][3] * arv[ni * 2 + 1];
            }
#pragma unroll
            for (int o = 1; o < 4; o <<= 1) {
                pel0 += __shfl_xor_sync(0xffffffffu, pel0, o);
                per0 += __shfl_xor_sync(0xffffffffu, per0, o);
                pel1 += __shfl_xor_sync(0xffffffffu, pel1, o);
                per1 += __shfl_xor_sync(0xffffffffu, per1, o);
            }
            if (cq == 0) {
                int rl = wm * 64 + mi * 16 + g;
                sEl[rl * 4 + wn] = pel0;
                sEr[rl * 4 + wn] = per0;
                sEl[(rl + 8) * 4 + wn] = pel1;
                sEr[(rl + 8) * 4 + wn] = per1;
            }
        }
        __syncthreads();
        if (tid < 128) {
            int r = brow + tid;
            if (r < M) {
                float4 e4 = *(float4*)&sEl[tid * 4];
                float4 r4 = *(float4*)&sEr[tid * 4];
                el[r] = e4.x + e4.y + e4.z + e4.w;
                er[r] = r4.x + r4.y + r4.z + r4.w;
            }
        }
    }
#undef ASM_
#undef BHM_
#undef BLM_
}

// ---------------- per-dst aggregation: out = relu((Σ ex z)/(Σ ex) + b) ------
template <int H, int D, bool FINAL>
__global__ void __launch_bounds__(256) k_agg(
    const float* __restrict__ z, const float* __restrict__ bias,
    const float* __restrict__ Wp, const float* __restrict__ bp,
    float* __restrict__ out) {
    constexpr int HD = H * D;
    constexpr int TPN = HD / 4;          // threads per node
    constexpr int NPB = 256 / TPN;       // nodes per block
    int t = threadIdx.x;
    int q = t % TPN;
    int n = blockIdx.x * NPB + t / TPN;
    int f = q * 4;
    int h = f / D;

    int s0 = g_rowstart[n];
    int deg = g_rowstart[n + 1] - s0;

    float4 acc = make_float4(0.f, 0.f, 0.f, 0.f);
    float ssum = 0.f;
    const int* csr = g_csr + s0;
    const float* exb = g_ex + (size_t)s0 * H + h;
#pragma unroll 4
    for (int j = 0; j < deg; j++) {
        int s = __ldg(csr + j);
        float exv = __ldg(exb + (size_t)j * H);
        float4 zv = *(const float4*)(z + (size_t)s * HD + f);
        ssum += exv;
        acc.x = fmaf(exv, zv.x, acc.x);
        acc.y = fmaf(exv, zv.y, acc.y);
        acc.z = fmaf(exv, zv.z, acc.z);
        acc.w = fmaf(exv, zv.w, acc.w);
    }
    float inv = (deg > 0) ? 1.0f / ssum : 0.f;
    float4 bv = *(const float4*)(bias + f);
    float4 v;
    v.x = fmaxf(acc.x * inv + bv.x, 0.f);
    v.y = fmaxf(acc.y * inv + bv.y, 0.f);
    v.z = fmaxf(acc.z * inv + bv.z, 0.f);
    v.w = fmaxf(acc.w * inv + bv.w, 0.f);

    if (!FINAL) {
        *(float4*)(out + (size_t)n * HD + f) = v;
    } else {
        float4 wv = *(const float4*)(Wp + f);
        float s = v.x * wv.x + v.y * wv.y + v.z * wv.z + v.w * wv.w;
#pragma unroll
        for (int o = 16; o; o >>= 1) s += __shfl_xor_sync(0xffffffffu, s, o);
        if (q == 0) out[n] = 1.0f / (1.0f + __expf(-(s + bp[0])));
    }
}

// ---------------- launch -----------------------------------------------------
extern "C" void kernel_launch(void* const* d_in, const int* in_sizes, int n_in,
                              void* d_out, int out_size) {
    (void)in_sizes; (void)n_in; (void)out_size;
    const float* features = (const float*)d_in[0];
    const int*   src      = (const int*)d_in[1];
    const int*   dst      = (const int*)d_in[2];
    // d_in[3] = edge_types (unused by forward)
    const float* W1 = (const float*)d_in[4];
    const float* al1 = (const float*)d_in[5];
    const float* ar1 = (const float*)d_in[6];
    const float* b1 = (const float*)d_in[7];
    const float* W2 = (const float*)d_in[8];
    const float* al2 = (const float*)d_in[9];
    const float* ar2 = (const float*)d_in[10];
    const float* b2 = (const float*)d_in[11];
    const float* W3 = (const float*)d_in[12];
    const float* al3 = (const float*)d_in[13];
    const float* ar3 = (const float*)d_in[14];
    const float* b3 = (const float*)d_in[15];
    const float* Wp = (const float*)d_in[16];
    const float* bp = (const float*)d_in[17];

    float *z, *x, *el, *er, *btH, *btL;
    int *counts, *cursor;
    cudaGetSymbolAddress((void**)&z, g_z);
    cudaGetSymbolAddress((void**)&x, g_x);
    cudaGetSymbolAddress((void**)&el, g_el);
    cudaGetSymbolAddress((void**)&er, g_er);
    cudaGetSymbolAddress((void**)&btH, g_btH);
    cudaGetSymbolAddress((void**)&btL, g_btL);
    cudaGetSymbolAddress((void**)&counts, g_counts);
    cudaGetSymbolAddress((void**)&cursor, g_cursor);

    float* btH1 = btH;            float* btL1 = btL;
    float* btH2 = btH + SZ1;      float* btL2 = btL + SZ1;
    float* btH3 = btH2 + SZ2;     float* btL3 = btL2 + SZ2;

    const int GB = (NN + 127) / 128;  // 782
    const int EB = (EE + 255) / 256;  // 6250

    cudaMemsetAsync(counts, 0, NN * sizeof(int));
    cudaMemsetAsync(cursor, 0, NN * sizeof(int));

    // 1-3: weight transposes + tf32 pre-split
    {
        dim3 b(32, 8);
        k_transpose<<<dim3(8, 8), b>>>(W1, btH1, btL1, 256, 256);
        k_transpose<<<dim3(4, 8), b>>>(W2, btH2, btL2, 256, 128);
        k_transpose<<<dim3(4, 4), b>>>(W3, btH3, btL3, 128, 128);
    }

    // 4: layer-1 GEMM (tf32x3) + fused scores + fused dst histogram [profiled]
    {
        dim3 g(GB, 2);
        k_mmagemm<8, 32, true><<<g, 256>>>(
            features, btH1, btL1, z, al1, ar1, el, er, dst, NN, 256, 256);
    }
    // 5: scan, 6: scatter + layer-1 edge exp
    k_scanA<<<1, 1024>>>();
    k_scatter_exp<<<EB, 256>>>(src, dst, el, er);

    // 7: layer-1 aggregation
    k_agg<8, 32, false><<<NN / 4, 256>>>(z, b1, nullptr, nullptr, x);

    // layer 2
    {
        dim3 g(GB, 1);
        k_mmagemm<4, 32, false><<<g, 256>>>(
            x, btH2, btL2, z, al2, ar2, el, er, nullptr, NN, 128, 256);
        k_edgeexp<4><<<EB, 256>>>(el, er);
        k_agg<4, 32, false><<<NN / 8, 256>>>(z, b2, nullptr, nullptr, x);
    }
    // layer 3 + fused prediction head
    {
        dim3 g(GB, 1);
        k_mmagemm<1, 128, false><<<g, 256>>>(
            x, btH3, btL3, z, al3, ar3, el, er, nullptr, NN, 128, 128);
        k_edgeexp<1><<<EB, 256>>>(el, er);
        k_agg<1, 128, true><<<NN / 8, 256>>>(z, b3, Wp, bp, (float*)d_out);
    }
}